// round 8
// baseline (speedup 1.0000x reference)
#include <cuda_runtime.h>
#include <cstdint>

#define EMBED_DIM   200
#define QUAD_DIM    50              // float4 chunks per row
#define NUM_LAYERS  3
#define NUM_WALKS   25
#define BATCH       8192
#define ROWS        76              // rows gathered per (pair, side)
#define PAIRS_CTA   8
#define SLOTS       (PAIRS_CTA * 2) // 16
#define ENTRIES     (SLOTS * ROWS)  // 1216
#define NBUCKETS    8               // idx >> 17 (71MB distinct/slice < 126MB L2)
#define NKEYS       (NBUCKETS * SLOTS) // 128
#define THREADS     256
#define GRID        (BATCH / PAIRS_CTA) // 1024 -> one resident wave

#define FMA4(A, W, V) do { \
    (A).x = fmaf((W), (V).x, (A).x); \
    (A).y = fmaf((W), (V).y, (A).y); \
    (A).z = fmaf((W), (V).z, (A).z); \
    (A).w = fmaf((W), (V).w, (A).w); } while (0)

#define LOADE(P, V) \
    float4 V = __ldg(emb4 + ((unsigned)(P) & 0xFFFFFu) * (unsigned)QUAD_DIM + j)

// Two runs processed together over their common prefix: 2 independent
// load->fma chains (MLP up to 8 with unroll 4), then short tails.
#define RUN2(A, B, K0, K1) do { \
    int _e0 = s_start[(K0)], _end0 = s_start[(K0) + 1]; \
    int _e1 = s_start[(K1)], _end1 = s_start[(K1) + 1]; \
    int _n  = min(_end0 - _e0, _end1 - _e1); \
    _Pragma("unroll 4") \
    for (int _i = 0; _i < _n; _i++) { \
        unsigned long long _p0 = s_sorted[_e0 + _i]; \
        unsigned long long _p1 = s_sorted[_e1 + _i]; \
        LOADE(_p0, _v0); LOADE(_p1, _v1); \
        FMA4(A, __uint_as_float((unsigned)(_p0 >> 32)), _v0); \
        FMA4(B, __uint_as_float((unsigned)(_p1 >> 32)), _v1); \
    } \
    _Pragma("unroll 4") \
    for (int _i = _e0 + _n; _i < _end0; _i++) { \
        unsigned long long _p = s_sorted[_i]; \
        LOADE(_p, _v); \
        FMA4(A, __uint_as_float((unsigned)(_p >> 32)), _v); \
    } \
    _Pragma("unroll 4") \
    for (int _i = _e1 + _n; _i < _end1; _i++) { \
        unsigned long long _p = s_sorted[_i]; \
        LOADE(_p, _v); \
        FMA4(B, __uint_as_float((unsigned)(_p >> 32)), _v); \
    } } while (0)

__global__ __launch_bounds__(THREADS, 7)
void gnp_bucket_kernel(const float* __restrict__ emb,
                       const float* __restrict__ layer_w,
                       const int*   __restrict__ uidx,
                       const int*   __restrict__ iidx,
                       const int*   __restrict__ uwalks,
                       const int*   __restrict__ iwalks,
                       float*       __restrict__ out)
{
    __shared__ unsigned long long s_entries[ENTRIES];
    __shared__ unsigned long long s_sorted[ENTRIES];
    __shared__ int   s_cnt[NKEYS];
    __shared__ int   s_scan[NKEYS];
    __shared__ int   s_start[NKEYS + 1];
    __shared__ int   s_pos[NKEYS];
    __shared__ float s_wc[4];
    __shared__ float s_red[8][2];

    const int t = threadIdx.x;
    const int pair_base = blockIdx.x * PAIRS_CTA;

    if (t == 0) {
        float w0 = layer_w[0], w1 = layer_w[1], w2 = layer_w[2], w3 = layer_w[3];
        float m  = fmaxf(fmaxf(w0, w1), fmaxf(w2, w3));
        float e0 = __expf(w0 - m), e1 = __expf(w1 - m);
        float e2 = __expf(w2 - m), e3 = __expf(w3 - m);
        float inv = 1.0f / (e0 + e1 + e2 + e3);
        s_wc[0] = e0 * inv;
        s_wc[1] = e1 * inv * (1.0f / NUM_WALKS);
        s_wc[2] = e2 * inv * (1.0f / NUM_WALKS);
        s_wc[3] = e3 * inv * (1.0f / NUM_WALKS);
    }
    if (t < NKEYS) s_cnt[t] = 0;
    __syncthreads();

    // ---- stage packed 64-bit entries + histogram over (bucket, slot) ----
    for (int e = t; e < ENTRIES; e += THREADS) {
        int s    = e / ROWS;            // slot 0..15
        int r    = e % ROWS;
        int side = s & 1;
        int b    = pair_base + (s >> 1);
        int idx;
        float w;
        if (r == 0) {
            idx = side ? iidx[b] : uidx[b];
            w   = s_wc[0];
        } else {
            int wk = (r - 1) / NUM_LAYERS;
            int l  = (r - 1) % NUM_LAYERS;
            const int* walks = side ? iwalks : uwalks;
            idx = walks[(b * NUM_WALKS + wk) * (NUM_LAYERS + 1) + l + 1];
            w   = s_wc[l + 1];
        }
        s_entries[e] = ((unsigned long long)__float_as_uint(w) << 32)
                     | (unsigned long long)((unsigned)idx | ((unsigned)s << 20));
        atomicAdd(&s_cnt[((idx >> 17) << 4) | s], 1);
    }
    __syncthreads();

    // ---- exclusive scan over 128 keys (Hillis-Steele in SMEM) ----
    if (t < NKEYS) s_scan[t] = s_cnt[t];
    __syncthreads();
    #pragma unroll
    for (int off = 1; off < NKEYS; off <<= 1) {
        int add = 0;
        if (t < NKEYS && t >= off) add = s_scan[t - off];
        __syncthreads();
        if (t < NKEYS) s_scan[t] += add;
        __syncthreads();
    }
    if (t < NKEYS) {
        s_start[t + 1] = s_scan[t];
        int st = (t == 0) ? 0 : s_scan[t - 1];
        s_start[t] = st;
        s_pos[t]   = st;
    }
    __syncthreads();

    // ---- scatter into (bucket, slot)-sorted order ----
    for (int e = t; e < ENTRIES; e += THREADS) {
        unsigned long long p = s_entries[e];
        unsigned lo = (unsigned)p;
        int key = ((int)((lo & 0xFFFFFu) >> 17) << 4) | ((int)(lo >> 20) & 15);
        s_sorted[atomicAdd(&s_pos[key], 1)] = p;
    }
    __syncthreads();

    // ---- phase-bucketed gather: quadrant q owns slots 4q..4q+3 ----
    const int q = t >> 6;
    const int j = t & 63;            // float4 chunk; j<50 active
    float4 a0 = make_float4(0.f, 0.f, 0.f, 0.f);
    float4 a1 = a0, a2 = a0, a3 = a0;
    const float4* __restrict__ emb4 = (const float4*)emb;

    if (j < QUAD_DIM) {
        #pragma unroll 1
        for (int k = 0; k < NBUCKETS; k++) {
            int kb = (k << 4) + (q << 2);
            RUN2(a0, a1, kb + 0, kb + 1);
            RUN2(a2, a3, kb + 2, kb + 3);
        }
    }

    // slots 4q/4q+1 = pair 2q (user/item); 4q+2/4q+3 = pair 2q+1
    float p0 = a0.x * a1.x + a0.y * a1.y + a0.z * a1.z + a0.w * a1.w;
    float p1 = a2.x * a3.x + a2.y * a3.y + a2.z * a3.z + a2.w * a3.w;

    #pragma unroll
    for (int o = 16; o > 0; o >>= 1) {
        p0 += __shfl_down_sync(0xffffffffu, p0, o);
        p1 += __shfl_down_sync(0xffffffffu, p1, o);
    }
    const int warp = t >> 5;
    if ((t & 31) == 0) { s_red[warp][0] = p0; s_red[warp][1] = p1; }
    __syncthreads();

    if (t < 8) {
        int qq = t >> 1, pr = t & 1;
        out[pair_base + 2 * qq + pr] =
            s_red[2 * qq][pr] + s_red[2 * qq + 1][pr];
    }
}

extern "C" void kernel_launch(void* const* d_in, const int* in_sizes, int n_in,
                              void* d_out, int out_size)
{
    const float* emb     = (const float*)d_in[0];
    const float* weights = (const float*)d_in[1];
    const int*   uidx    = (const int*)  d_in[2];
    const int*   iidx    = (const int*)  d_in[3];
    const int*   uwalks  = (const int*)  d_in[4];
    const int*   iwalks  = (const int*)  d_in[5];
    float*       out     = (float*)d_out;

    gnp_bucket_kernel<<<GRID, THREADS>>>(emb, weights, uidx, iidx,
                                         uwalks, iwalks, out);
}

// round 9
// speedup vs baseline: 1.3107x; 1.3107x over previous
#include <cuda_runtime.h>
#include <cstdint>

#define EMBED_DIM   200
#define QUAD_DIM    50              // float4 chunks per row
#define NUM_LAYERS  3
#define NUM_WALKS   25
#define BATCH       8192
#define ROWS        76              // rows gathered per (pair, side)
#define PAIRS_CTA   8
#define SLOTS       (PAIRS_CTA * 2) // 16
#define ENTRIES     (SLOTS * ROWS)  // 1216
#define NBUCKETS    16              // idx >> 16 -> ~36MB slice; drift window fits L2
#define NKEYS       (NBUCKETS * SLOTS) // 256
#define THREADS     256
#define GRID        (BATCH / PAIRS_CTA) // 1024 -> one resident wave @ occ 7

#define FMA4(A, W, V) do { \
    (A).x = fmaf((W), (V).x, (A).x); \
    (A).y = fmaf((W), (V).y, (A).y); \
    (A).z = fmaf((W), (V).z, (A).z); \
    (A).w = fmaf((W), (V).w, (A).w); } while (0)

// One sorted run with a fixed accumulator: branch-free hot loop.
#define RUN(ACC, KEY) do { \
    int _e = s_start[(KEY)]; \
    int _end = s_start[(KEY) + 1]; \
    _Pragma("unroll 4") \
    for (; _e < _end; _e++) { \
        unsigned _p = s_sorted[_e]; \
        float _w = s_wc[(_p >> 24) & 3u]; \
        float4 _v = __ldg(emb4 + (_p & 0xFFFFFu) * (unsigned)QUAD_DIM + j); \
        FMA4(ACC, _w, _v); \
    } } while (0)

__global__ __launch_bounds__(THREADS, 7)
void gnp_bucket_kernel(const float* __restrict__ emb,
                       const float* __restrict__ layer_w,
                       const int*   __restrict__ uidx,
                       const int*   __restrict__ iidx,
                       const int*   __restrict__ uwalks,
                       const int*   __restrict__ iwalks,
                       float*       __restrict__ out)
{
    __shared__ unsigned s_entries[ENTRIES];
    __shared__ unsigned s_sorted[ENTRIES];
    __shared__ int      s_cnt[NKEYS];
    __shared__ int      s_scan[NKEYS];
    __shared__ int      s_start[NKEYS + 1];
    __shared__ int      s_pos[NKEYS];
    __shared__ float    s_wc[4];
    __shared__ float    s_red[8][2];

    const int t = threadIdx.x;
    const int pair_base = blockIdx.x * PAIRS_CTA;

    if (t == 0) {
        float w0 = layer_w[0], w1 = layer_w[1], w2 = layer_w[2], w3 = layer_w[3];
        float m  = fmaxf(fmaxf(w0, w1), fmaxf(w2, w3));
        float e0 = __expf(w0 - m), e1 = __expf(w1 - m);
        float e2 = __expf(w2 - m), e3 = __expf(w3 - m);
        float inv = 1.0f / (e0 + e1 + e2 + e3);
        s_wc[0] = e0 * inv;
        s_wc[1] = e1 * inv * (1.0f / NUM_WALKS);
        s_wc[2] = e2 * inv * (1.0f / NUM_WALKS);
        s_wc[3] = e3 * inv * (1.0f / NUM_WALKS);
    }
    if (t < NKEYS) s_cnt[t] = 0;
    __syncthreads();

    // ---- stage packed entries + histogram over (bucket, slot) ----
    for (int e = t; e < ENTRIES; e += THREADS) {
        int s    = e / ROWS;            // slot 0..15
        int r    = e % ROWS;
        int side = s & 1;
        int b    = pair_base + (s >> 1);
        int idx, wc;
        if (r == 0) {
            idx = side ? iidx[b] : uidx[b];
            wc  = 0;
        } else {
            int w = (r - 1) / NUM_LAYERS;
            int l = (r - 1) % NUM_LAYERS;
            const int* walks = side ? iwalks : uwalks;
            idx = walks[(b * NUM_WALKS + w) * (NUM_LAYERS + 1) + l + 1];
            wc  = l + 1;
        }
        s_entries[e] = (unsigned)idx | ((unsigned)s << 20) | ((unsigned)wc << 24);
        atomicAdd(&s_cnt[((idx >> 16) << 4) | s], 1);
    }
    __syncthreads();

    // ---- exclusive scan over 256 keys (Hillis-Steele in SMEM) ----
    if (t < NKEYS) s_scan[t] = s_cnt[t];
    __syncthreads();
    #pragma unroll
    for (int off = 1; off < NKEYS; off <<= 1) {
        int add = 0;
        if (t < NKEYS && t >= off) add = s_scan[t - off];
        __syncthreads();
        if (t < NKEYS) s_scan[t] += add;
        __syncthreads();
    }
    if (t < NKEYS) {
        s_start[t + 1] = s_scan[t];
        int st = (t == 0) ? 0 : s_scan[t - 1];
        s_start[t] = st;
        s_pos[t]   = st;
    }
    __syncthreads();

    // ---- scatter into (bucket, slot)-sorted order ----
    for (int e = t; e < ENTRIES; e += THREADS) {
        unsigned p = s_entries[e];
        int key = ((int)((p & 0xFFFFFu) >> 16) << 4) | ((int)(p >> 20) & 15);
        s_sorted[atomicAdd(&s_pos[key], 1)] = p;
    }
    __syncthreads();

    // ---- phase-bucketed gather: quadrant q owns slots 4q..4q+3 ----
    const int q = t >> 6;
    const int j = t & 63;            // float4 chunk; j<50 active
    float4 a0 = make_float4(0.f, 0.f, 0.f, 0.f);
    float4 a1 = a0, a2 = a0, a3 = a0;
    const float4* __restrict__ emb4 = (const float4*)emb;

    if (j < QUAD_DIM) {
        #pragma unroll 1
        for (int k = 0; k < NBUCKETS; k++) {
            int kb = (k << 4) + (q << 2);
            RUN(a0, kb + 0);
            RUN(a1, kb + 1);
            RUN(a2, kb + 2);
            RUN(a3, kb + 3);
        }
    }

    // slots 4q/4q+1 = pair 2q (user/item); 4q+2/4q+3 = pair 2q+1
    float p0 = a0.x * a1.x + a0.y * a1.y + a0.z * a1.z + a0.w * a1.w;
    float p1 = a2.x * a3.x + a2.y * a3.y + a2.z * a3.z + a2.w * a3.w;

    #pragma unroll
    for (int o = 16; o > 0; o >>= 1) {
        p0 += __shfl_down_sync(0xffffffffu, p0, o);
        p1 += __shfl_down_sync(0xffffffffu, p1, o);
    }
    const int warp = t >> 5;
    if ((t & 31) == 0) { s_red[warp][0] = p0; s_red[warp][1] = p1; }
    __syncthreads();

    if (t < 8) {
        int qq = t >> 1, pr = t & 1;
        out[pair_base + 2 * qq + pr] =
            s_red[2 * qq][pr] + s_red[2 * qq + 1][pr];
    }
}

extern "C" void kernel_launch(void* const* d_in, const int* in_sizes, int n_in,
                              void* d_out, int out_size)
{
    const float* emb     = (const float*)d_in[0];
    const float* weights = (const float*)d_in[1];
    const int*   uidx    = (const int*)  d_in[2];
    const int*   iidx    = (const int*)  d_in[3];
    const int*   uwalks  = (const int*)  d_in[4];
    const int*   iwalks  = (const int*)  d_in[5];
    float*       out     = (float*)d_out;

    gnp_bucket_kernel<<<GRID, THREADS>>>(emb, weights, uidx, iidx,
                                         uwalks, iwalks, out);
}